// round 1
// baseline (speedup 1.0000x reference)
#include <cuda_runtime.h>
#include <cstddef>

// Problem constants (fixed shapes for this problem; N derived at runtime)
#define CIN   256
#define CB    128
#define COUT  512
#define KNB   27
#define NMAX  61440      // >= 60000, multiple of 128
#define NPART 256        // partial-sum blocks for column stats

// ---------------------------------------------------------------------------
// Scratch (device globals; no cudaMalloc allowed)
// ---------------------------------------------------------------------------
__device__ float g_c1[NMAX * CB];          // pre-BN output of 1x1 conv a   [N, CB]
__device__ float g_c2[NMAX * CB];          // pre-BN output of octree conv  [N, CB]
__device__ float g_c3[NMAX * COUT];        // pre-BN output of 1x1 conv b   [N, COUT]
__device__ float g_sc[NMAX * COUT];        // pre-BN shortcut               [N, COUT]
__device__ float g_ps[NPART * COUT];       // partial sums
__device__ float g_pq[NPART * COUT];       // partial sums of squares
__device__ float g_s1[CB],  g_t1[CB];      // BN1 scale/shift
__device__ float g_s2[CB],  g_t2[CB];      // BN3 scale/shift
__device__ float g_s3[COUT], g_t3[COUT];   // BN1b scale/shift
__device__ float g_s4[COUT], g_t4[COUT];   // BNc scale/shift

// ---------------------------------------------------------------------------
// GEMM: out[N, J] = x^T @ W^T,  A[m,k] = x[k*N + m] (x is [KDIM, N]),
// B[k,j] = W[j*KDIM + k] (W is [J, KDIM] row-major).
// Tile 128(M) x 64(J) x 16(K), 256 threads, 8x4 micro-tile.
// ---------------------------------------------------------------------------
template<int KDIM>
__global__ __launch_bounds__(256, 2)
void gemm_xw_kernel(const float* __restrict__ x, const float* __restrict__ W,
                    float* __restrict__ out, int N, int ldc)
{
    __shared__ float As[16][128];
    __shared__ float Bs[16][64];
    const int m0 = blockIdx.x * 128;
    const int j0 = blockIdx.y * 64;
    const int t  = threadIdx.x;
    const int tx = t & 15;        // covers J via {tx, tx+16, tx+32, tx+48}
    const int ty = t >> 4;        // covers M via {ty, ty+16, ..., ty+112}

    float acc[8][4];
#pragma unroll
    for (int i = 0; i < 8; i++)
#pragma unroll
        for (int j = 0; j < 4; j++) acc[i][j] = 0.f;

    for (int k0 = 0; k0 < KDIM; k0 += 16) {
        // A tile: 128x16, coalesced along m (x column-contiguous in m)
#pragma unroll
        for (int i = 0; i < 8; i++) {
            int idx = i * 256 + t;
            int m = idx & 127, k = idx >> 7;
            int gm = m0 + m;
            As[k][m] = (gm < N) ? x[(size_t)(k0 + k) * N + gm] : 0.f;
        }
        // B tile: 16x64
#pragma unroll
        for (int i = 0; i < 4; i++) {
            int idx = i * 256 + t;
            int k = idx & 15, j = idx >> 4;
            Bs[k][j] = W[(size_t)(j0 + j) * KDIM + (k0 + k)];
        }
        __syncthreads();
#pragma unroll
        for (int kk = 0; kk < 16; kk++) {
            float a[8], b[4];
#pragma unroll
            for (int i = 0; i < 8; i++) a[i] = As[kk][ty + i * 16];
#pragma unroll
            for (int j = 0; j < 4; j++) b[j] = Bs[kk][tx + j * 16];
#pragma unroll
            for (int i = 0; i < 8; i++)
#pragma unroll
                for (int j = 0; j < 4; j++)
                    acc[i][j] = fmaf(a[i], b[j], acc[i][j]);
        }
        __syncthreads();
    }
#pragma unroll
    for (int i = 0; i < 8; i++) {
        int gm = m0 + ty + i * 16;
        if (gm < N) {
#pragma unroll
            for (int j = 0; j < 4; j++)
                out[(size_t)gm * ldc + j0 + tx + j * 16] = acc[i][j];
        }
    }
}

// ---------------------------------------------------------------------------
// GEMM with BN+ReLU applied to A on load:
// out[N, J] = relu(bn(A)) @ W^T,  A is [N, KDIM] row-major.
// ---------------------------------------------------------------------------
template<int KDIM>
__global__ __launch_bounds__(256, 2)
void gemm_act_kernel(const float* __restrict__ A, const float* __restrict__ W,
                     const float* __restrict__ scl, const float* __restrict__ sft,
                     float* __restrict__ out, int N, int ldc)
{
    __shared__ float As[16][129];   // pad 1: conflict-free transpose store
    __shared__ float Bs[16][64];
    const int m0 = blockIdx.x * 128;
    const int j0 = blockIdx.y * 64;
    const int t  = threadIdx.x;
    const int tx = t & 15;
    const int ty = t >> 4;

    float acc[8][4];
#pragma unroll
    for (int i = 0; i < 8; i++)
#pragma unroll
        for (int j = 0; j < 4; j++) acc[i][j] = 0.f;

    for (int k0 = 0; k0 < KDIM; k0 += 16) {
        // A tile: read row-major (k fast, coalesced 64B/row), store transposed
#pragma unroll
        for (int i = 0; i < 8; i++) {
            int idx = i * 256 + t;
            int k = idx & 15, m = idx >> 4;
            int gm = m0 + m;
            float v = 0.f;
            if (gm < N) {
                v = fmaf(A[(size_t)gm * KDIM + k0 + k], scl[k0 + k], sft[k0 + k]);
                v = fmaxf(v, 0.f);
            }
            As[k][m] = v;
        }
#pragma unroll
        for (int i = 0; i < 4; i++) {
            int idx = i * 256 + t;
            int k = idx & 15, j = idx >> 4;
            Bs[k][j] = W[(size_t)(j0 + j) * KDIM + (k0 + k)];
        }
        __syncthreads();
#pragma unroll
        for (int kk = 0; kk < 16; kk++) {
            float a[8], b[4];
#pragma unroll
            for (int i = 0; i < 8; i++) a[i] = As[kk][ty + i * 16];
#pragma unroll
            for (int j = 0; j < 4; j++) b[j] = Bs[kk][tx + j * 16];
#pragma unroll
            for (int i = 0; i < 8; i++)
#pragma unroll
                for (int j = 0; j < 4; j++)
                    acc[i][j] = fmaf(a[i], b[j], acc[i][j]);
        }
        __syncthreads();
    }
#pragma unroll
    for (int i = 0; i < 8; i++) {
        int gm = m0 + ty + i * 16;
        if (gm < N) {
#pragma unroll
            for (int j = 0; j < 4; j++)
                out[(size_t)gm * ldc + j0 + tx + j * 16] = acc[i][j];
        }
    }
}

// ---------------------------------------------------------------------------
// Octree conv: c2[n,d] = sum_k sum_c relu(bn(c1))[neigh[n,k], c] * W3[k,c,d]
// Empty neighbor (idx == N) contributes exact zeros.
// Tile 128(M) x 128(D), K-chunk 16, 256 threads, 8x8 micro-tile.
// ---------------------------------------------------------------------------
__global__ __launch_bounds__(256, 2)
void conv_octree_kernel(const float* __restrict__ c1, const int* __restrict__ neigh,
                        const float* __restrict__ W3,
                        const float* __restrict__ scl, const float* __restrict__ sft,
                        float* __restrict__ out, int N)
{
    __shared__ float As[16][129];
    __shared__ float Bs[16][128];
    __shared__ int   ngs[128];
    __shared__ float s_scl[128], s_sft[128];

    const int m0 = blockIdx.x * 128;
    const int t  = threadIdx.x;
    const int tx = t & 15;     // D via {tx + 16j}
    const int ty = t >> 4;     // M via {ty + 16i}

    if (t < 128) { s_scl[t] = scl[t]; s_sft[t] = sft[t]; }

    float acc[8][8];
#pragma unroll
    for (int i = 0; i < 8; i++)
#pragma unroll
        for (int j = 0; j < 8; j++) acc[i][j] = 0.f;

    for (int k = 0; k < KNB; k++) {
        if (t < 128) {
            int gm = m0 + t;
            ngs[t] = (gm < N) ? neigh[(size_t)gm * KNB + k] : N;  // N == empty
        }
        __syncthreads();
        const float* Wk = W3 + (size_t)k * CB * CB;

        for (int c0 = 0; c0 < CB; c0 += 16) {
            // Gather A tile: 128 rows x 16 channels (64B contiguous per row)
#pragma unroll
            for (int i = 0; i < 8; i++) {
                int idx = i * 256 + t;
                int c = idx & 15, m = idx >> 4;
                int ng = ngs[m];
                float v = 0.f;
                if (ng < N) {
                    v = fmaf(c1[(size_t)ng * CB + c0 + c], s_scl[c0 + c], s_sft[c0 + c]);
                    v = fmaxf(v, 0.f);
                }
                As[c][m] = v;
            }
            // B tile: W3[k][c0..c0+16, 0..128], coalesced
#pragma unroll
            for (int i = 0; i < 8; i++) {
                int idx = i * 256 + t;
                int j = idx & 127, kc = idx >> 7;
                Bs[kc][j] = Wk[(size_t)(c0 + kc) * CB + j];
            }
            __syncthreads();
#pragma unroll
            for (int kk = 0; kk < 16; kk++) {
                float a[8], b[8];
#pragma unroll
                for (int i = 0; i < 8; i++) a[i] = As[kk][ty + i * 16];
#pragma unroll
                for (int j = 0; j < 8; j++) b[j] = Bs[kk][tx + j * 16];
#pragma unroll
                for (int i = 0; i < 8; i++)
#pragma unroll
                    for (int j = 0; j < 8; j++)
                        acc[i][j] = fmaf(a[i], b[j], acc[i][j]);
            }
            __syncthreads();
        }
    }
#pragma unroll
    for (int i = 0; i < 8; i++) {
        int gm = m0 + ty + i * 16;
        if (gm < N) {
#pragma unroll
            for (int j = 0; j < 8; j++)
                out[(size_t)gm * CB + tx + j * 16] = acc[i][j];
        }
    }
}

// ---------------------------------------------------------------------------
// Column statistics (deterministic 2-level reduction)
// ---------------------------------------------------------------------------
template<int C>
__global__ void col_partial_kernel(const float* __restrict__ A, int N,
                                   float* __restrict__ ps, float* __restrict__ pq)
{
    const int b = blockIdx.x;
    const int rows = (N + NPART - 1) / NPART;
    const int r0 = b * rows;
    const int r1 = (r0 + rows < N) ? (r0 + rows) : N;
    const int t = threadIdx.x;
    for (int c = t; c < C; c += 256) {
        float s0 = 0.f, s1 = 0.f, q0 = 0.f, q1 = 0.f;
        int r = r0;
        for (; r + 1 < r1; r += 2) {
            float v0 = A[(size_t)r * C + c];
            float v1 = A[(size_t)(r + 1) * C + c];
            s0 += v0; q0 = fmaf(v0, v0, q0);
            s1 += v1; q1 = fmaf(v1, v1, q1);
        }
        if (r < r1) {
            float v = A[(size_t)r * C + c];
            s0 += v; q0 = fmaf(v, v, q0);
        }
        ps[b * C + c] = s0 + s1;
        pq[b * C + c] = q0 + q1;
    }
}

template<int C>
__global__ void col_finalize_kernel(const float* __restrict__ ps, const float* __restrict__ pq,
                                    const float* __restrict__ g, const float* __restrict__ bta,
                                    float* __restrict__ scl, float* __restrict__ sft, int N)
{
    int c = blockIdx.x * blockDim.x + threadIdx.x;
    if (c >= C) return;
    float s = 0.f, q = 0.f;
    for (int b = 0; b < NPART; b++) { s += ps[b * C + c]; q += pq[b * C + c]; }
    float inv_n = 1.f / (float)N;
    float mu  = s * inv_n;
    float var = fmaf(-mu, mu, q * inv_n);
    float sc  = g[c] * rsqrtf(var + 1e-5f);
    scl[c] = sc;
    sft[c] = fmaf(-mu, sc, bta[c]);
}

// ---------------------------------------------------------------------------
// Final: out[e, n] = relu(bn(c3)[n,e] + bn(sc)[n,e]), transposed write
// ---------------------------------------------------------------------------
__global__ void final_out_kernel(const float* __restrict__ c3, const float* __restrict__ sc,
                                 const float* __restrict__ s3, const float* __restrict__ t3,
                                 const float* __restrict__ s4, const float* __restrict__ t4,
                                 float* __restrict__ out, int N)
{
    __shared__ float sm[32][33];
    const int n0 = blockIdx.x * 32;
    const int e0 = blockIdx.y * 32;
    const int tx = threadIdx.x;   // 32
    const int ty = threadIdx.y;   // 8
    const int e  = e0 + tx;
    const float a3 = s3[e], b3v = t3[e], a4 = s4[e], b4v = t4[e];

#pragma unroll
    for (int yy = 0; yy < 32; yy += 8) {
        int n = n0 + ty + yy;
        float v = 0.f;
        if (n < N) {
            float p = fmaf(c3[(size_t)n * COUT + e], a3, b3v);
            float q = fmaf(sc[(size_t)n * COUT + e], a4, b4v);
            v = fmaxf(p + q, 0.f);
        }
        sm[tx][ty + yy] = v;
    }
    __syncthreads();
#pragma unroll
    for (int yy = 0; yy < 32; yy += 8) {
        int eo = e0 + ty + yy;
        int n  = n0 + tx;
        if (n < N) out[(size_t)eo * N + n] = sm[ty + yy][tx];
    }
}

// ---------------------------------------------------------------------------
// Launcher
// ---------------------------------------------------------------------------
template<class T>
static float* sym_addr(T& s) { void* p = nullptr; cudaGetSymbolAddress(&p, s); return (float*)p; }

extern "C" void kernel_launch(void* const* d_in, const int* in_sizes, int n_in,
                              void* d_out, int out_size)
{
    const float* x   = (const float*)d_in[0];
    const int*   ngh = (const int*)  d_in[1];
    const float* W1a = (const float*)d_in[2];
    const float* g1a = (const float*)d_in[3];
    const float* b1a = (const float*)d_in[4];
    const float* W3  = (const float*)d_in[5];
    const float* g3  = (const float*)d_in[6];
    const float* b3  = (const float*)d_in[7];
    const float* W1b = (const float*)d_in[8];
    const float* g1b = (const float*)d_in[9];
    const float* b1b = (const float*)d_in[10];
    const float* Wc  = (const float*)d_in[11];
    const float* gc  = (const float*)d_in[12];
    const float* bc  = (const float*)d_in[13];
    float* out = (float*)d_out;

    const int N = in_sizes[1] / KNB;
    if (N <= 0 || N > NMAX) return;

    float* c1  = sym_addr(g_c1);
    float* c2  = sym_addr(g_c2);
    float* c3  = sym_addr(g_c3);
    float* scv = sym_addr(g_sc);
    float* ps  = sym_addr(g_ps);
    float* pq  = sym_addr(g_pq);
    float* s1  = sym_addr(g_s1); float* t1 = sym_addr(g_t1);
    float* s2  = sym_addr(g_s2); float* t2 = sym_addr(g_t2);
    float* s3  = sym_addr(g_s3); float* t3 = sym_addr(g_t3);
    float* s4  = sym_addr(g_s4); float* t4 = sym_addr(g_t4);

    const int mb = (N + 127) / 128;

    // c1pre = h @ W1a^T
    gemm_xw_kernel<CIN><<<dim3(mb, CB / 64), 256>>>(x, W1a, c1, N, CB);
    col_partial_kernel<CB><<<NPART, 256>>>(c1, N, ps, pq);
    col_finalize_kernel<CB><<<1, CB>>>(ps, pq, g1a, b1a, s1, t1, N);

    // c2pre = octree_conv(relu(bn(c1pre)))
    conv_octree_kernel<<<mb, 256>>>(c1, ngh, W3, s1, t1, c2, N);
    col_partial_kernel<CB><<<NPART, 256>>>(c2, N, ps, pq);
    col_finalize_kernel<CB><<<1, CB>>>(ps, pq, g3, b3, s2, t2, N);

    // c3pre = relu(bn(c2pre)) @ W1b^T
    gemm_act_kernel<CB><<<dim3(mb, COUT / 64), 256>>>(c2, W1b, s2, t2, c3, N, COUT);
    // scpre = h @ Wc^T
    gemm_xw_kernel<CIN><<<dim3(mb, COUT / 64), 256>>>(x, Wc, scv, N, COUT);

    col_partial_kernel<COUT><<<NPART, 256>>>(c3, N, ps, pq);
    col_finalize_kernel<COUT><<<2, 256>>>(ps, pq, g1b, b1b, s3, t3, N);
    col_partial_kernel<COUT><<<NPART, 256>>>(scv, N, ps, pq);
    col_finalize_kernel<COUT><<<2, 256>>>(ps, pq, gc, bc, s4, t4, N);

    // out = relu(bn(c3pre) + bn(scpre))^T
    final_out_kernel<<<dim3((N + 31) / 32, COUT / 32), dim3(32, 8)>>>(
        c3, scv, s3, t3, s4, t4, out, N);
}

// round 8
// speedup vs baseline: 2.5194x; 2.5194x over previous
#include <cuda_runtime.h>
#include <cstdint>
#include <cstddef>

#define CIN   256
#define CB    128
#define COUT  512
#define KNB   27
#define NMAX  61440
#define NPART 256

// SMEM tile: [128 rows][36 floats] (32 data + 4 pad), double-buffered A+B
#define ROWF  36
static constexpr int STAGE_BYTES = 128 * ROWF * 4;             // 18432 per tile
static constexpr int DSMEM_BYTES = 4 * STAGE_BYTES + 256;      // 2 stages x (A+B)

// ---------------------------------------------------------------------------
// Scratch (device globals; no cudaMalloc allowed)
// ---------------------------------------------------------------------------
__device__ float g_h  [NMAX * CIN];        // x transposed -> [N, Cin]
__device__ float g_c1 [NMAX * CB];         // pre-BN conv1a out [N, CB]
__device__ float g_a1 [NMAX * CB];         // relu(bn(c1))      [N, CB]
__device__ float g_c2 [NMAX * CB];         // pre-BN octree out [N, CB]
__device__ float g_a2 [NMAX * CB];         // relu(bn(c2))      [N, CB]
__device__ float g_c3 [NMAX * COUT];       // pre-BN conv1b out [N, COUT]
__device__ float g_sc [NMAX * COUT];       // pre-BN shortcut   [N, COUT]
__device__ float g_W3t[KNB * CB * CB];     // W3 transposed per tap: [k][d][c]
__device__ float g_ps [NPART * COUT];
__device__ float g_pq [NPART * COUT];
__device__ float g_s1[CB],   g_t1[CB];
__device__ float g_s2[CB],   g_t2[CB];
__device__ float g_s3[COUT], g_t3[COUT];
__device__ float g_s4[COUT], g_t4[COUT];

// ---------------------------------------------------------------------------
// PTX helpers (baseline PTX only — no arch-specific 'a' features)
// ---------------------------------------------------------------------------
__device__ __forceinline__ uint32_t smem_u32(const void* p) {
    uint32_t a;
    asm("{ .reg .u64 t; cvta.to.shared.u64 t, %1; cvt.u32.u64 %0, t; }" : "=r"(a) : "l"(p));
    return a;
}
__device__ __forceinline__ void cp_async16(uint32_t dst, const void* src, bool pred) {
    int sz = pred ? 16 : 0;
    asm volatile("cp.async.cg.shared.global [%0], [%1], 16, %2;"
                 :: "r"(dst), "l"(src), "r"(sz) : "memory");
}
#define CP_COMMIT() asm volatile("cp.async.commit_group;" ::: "memory")
#define CP_WAIT1()  asm volatile("cp.async.wait_group 1;" ::: "memory")
#define CP_WAIT0()  asm volatile("cp.async.wait_group 0;" ::: "memory")

__device__ __forceinline__ uint32_t f2tf32(float x) {
    uint32_t r;
    asm("cvt.rna.tf32.f32 %0, %1;" : "=r"(r) : "f"(x));
    return r;
}
__device__ __forceinline__ void mma1688(float* d, const uint32_t* a, const uint32_t* b) {
    asm volatile(
        "mma.sync.aligned.m16n8k8.row.col.f32.tf32.tf32.f32 "
        "{%0,%1,%2,%3}, {%4,%5,%6,%7}, {%8,%9}, {%0,%1,%2,%3};"
        : "+f"(d[0]), "+f"(d[1]), "+f"(d[2]), "+f"(d[3])
        : "r"(a[0]), "r"(a[1]), "r"(a[2]), "r"(a[3]), "r"(b[0]), "r"(b[1]));
}

// ---------------------------------------------------------------------------
// Unified tf32 mma.sync GEMM.
// MODE 0: out[m, j] = sum_k A[m,k] * B[j,k];  A row-major [N, KDIM].
// MODE 1: octree conv: A rows gathered via neigh (tap-major), B = W3t[tap],
//         contraction over 27 taps x CB channels. Empty neighbor -> zeros.
// Block tile 128(M) x 128(J) x 32(K); 8 warps (2x4); warp tile 64x32.
// ---------------------------------------------------------------------------
template<int MODE, int KDIM>
__global__ __launch_bounds__(256, 1)
void mma_gemm_kernel(const float* __restrict__ A, const float* __restrict__ B,
                     const int* __restrict__ neigh,
                     float* __restrict__ out, int N, int ldc)
{
    constexpr int NCH = (MODE == 1) ? KNB * (CB / 32) : KDIM / 32;

    extern __shared__ float smem[];
    float* As[2] = { smem,                  smem + 2 * 128 * ROWF };
    float* Bs[2] = { smem + 128 * ROWF,     smem + 3 * 128 * ROWF };
    uint32_t as_u[2] = { smem_u32(As[0]), smem_u32(As[1]) };
    uint32_t bs_u[2] = { smem_u32(Bs[0]), smem_u32(Bs[1]) };

    const int t    = threadIdx.x;
    const int wid  = t >> 5;
    const int lane = t & 31;
    const int wm   = wid & 1;          // 2 warp-rows
    const int wn   = wid >> 1;         // 4 warp-cols
    const int m0   = blockIdx.x * 128;
    const int j0   = blockIdx.y * 128;

    // copy-lane mapping: each thread handles 4 rows x one 16B segment
    const int cm = t >> 3;             // row slot 0..31 (x4 via i)
    const int cv = t & 7;              // 16B segment 0..7

    float acc[4][4][4];
#pragma unroll
    for (int mi = 0; mi < 4; mi++)
#pragma unroll
        for (int ni = 0; ni < 4; ni++)
#pragma unroll
            for (int q = 0; q < 4; q++) acc[mi][ni][q] = 0.f;

    // ---- chunk copy (cp.async) ----
    auto issue_copy = [&](int ch, int stg) {
        int tap, c0;
        if (MODE == 1) { tap = ch >> 2; c0 = (ch & 3) * 32; }
        else           { tap = 0;       c0 = ch * 32; }
        const float* Bg = (MODE == 1) ? (B + (size_t)tap * CB * CB) : B;
        constexpr int KB = (MODE == 1) ? CB : KDIM;

#pragma unroll
        for (int i = 0; i < 4; i++) {
            int m = i * 32 + cm;
            int gm = m0 + m;
            const float* src;
            bool pred;
            if (MODE == 1) {
                int ng = (gm < N) ? neigh[(size_t)gm * KNB + tap] : N;
                pred = (ng < N);
                src  = A + (size_t)(pred ? ng : 0) * CB + c0 + cv * 4;
            } else {
                pred = (gm < N);
                src  = A + (size_t)(pred ? gm : 0) * KDIM + c0 + cv * 4;
            }
            cp_async16(as_u[stg] + (uint32_t)(m * ROWF + cv * 4) * 4u, src, pred);
        }
#pragma unroll
        for (int i = 0; i < 4; i++) {
            int j = i * 32 + cm;
            const float* src = Bg + (size_t)(j0 + j) * KB + c0 + cv * 4;
            cp_async16(bs_u[stg] + (uint32_t)(j * ROWF + cv * 4) * 4u, src, true);
        }
        CP_COMMIT();
    };

    issue_copy(0, 0);

    for (int ch = 0; ch < NCH; ch++) {
        const int stg = ch & 1;
        if (ch + 1 < NCH) { issue_copy(ch + 1, stg ^ 1); CP_WAIT1(); }
        else              { CP_WAIT0(); }
        __syncthreads();

        const float* Ab = As[stg];
        const float* Bb = Bs[stg];
        const int ar = wm * 64 + (lane >> 2);      // + mi*16 (+8)
        const int bn = wn * 32 + (lane >> 2);      // + ni*8

#pragma unroll
        for (int kk = 0; kk < 4; kk++) {
            const int kc = kk * 8 + (lane & 3);
            uint32_t af[4][4], bf[4][2];
#pragma unroll
            for (int mi = 0; mi < 4; mi++) {
                const float* p = Ab + (ar + mi * 16) * ROWF + kc;
                af[mi][0] = f2tf32(p[0]);
                af[mi][1] = f2tf32(p[8 * ROWF]);
                af[mi][2] = f2tf32(p[4]);
                af[mi][3] = f2tf32(p[8 * ROWF + 4]);
            }
#pragma unroll
            for (int ni = 0; ni < 4; ni++) {
                const float* p = Bb + (bn + ni * 8) * ROWF + kc;
                bf[ni][0] = f2tf32(p[0]);
                bf[ni][1] = f2tf32(p[4]);
            }
#pragma unroll
            for (int mi = 0; mi < 4; mi++)
#pragma unroll
                for (int ni = 0; ni < 4; ni++)
                    mma1688(acc[mi][ni], af[mi], bf[ni]);
        }
        __syncthreads();
    }

    // ---- epilogue ----
    const int er = m0 + wm * 64 + (lane >> 2);
    const int ec = j0 + wn * 32 + 2 * (lane & 3);
#pragma unroll
    for (int mi = 0; mi < 4; mi++) {
        int r0 = er + mi * 16, r1 = r0 + 8;
#pragma unroll
        for (int ni = 0; ni < 4; ni++) {
            int c = ec + ni * 8;
            if (r0 < N)
                *reinterpret_cast<float2*>(out + (size_t)r0 * ldc + c) =
                    make_float2(acc[mi][ni][0], acc[mi][ni][1]);
            if (r1 < N)
                *reinterpret_cast<float2*>(out + (size_t)r1 * ldc + c) =
                    make_float2(acc[mi][ni][2], acc[mi][ni][3]);
        }
    }
}

// ---------------------------------------------------------------------------
// Transposes
// ---------------------------------------------------------------------------
__global__ void transpose_x_kernel(const float* __restrict__ x, float* __restrict__ h, int N)
{
    __shared__ float sm[32][33];
    const int n0 = blockIdx.x * 32;
    const int c0 = blockIdx.y * 32;
    const int tx = threadIdx.x, ty = threadIdx.y;
#pragma unroll
    for (int yy = 0; yy < 32; yy += 8) {
        int n = n0 + tx;
        sm[ty + yy][tx] = (n < N) ? x[(size_t)(c0 + ty + yy) * N + n] : 0.f;
    }
    __syncthreads();
#pragma unroll
    for (int yy = 0; yy < 32; yy += 8) {
        int n = n0 + ty + yy;
        if (n < N) h[(size_t)n * CIN + c0 + tx] = sm[tx][ty + yy];
    }
}

__global__ void transpose_w3_kernel(const float* __restrict__ W3, float* __restrict__ W3t)
{
    __shared__ float sm[32][33];
    const int k  = blockIdx.x;
    const int c0 = blockIdx.y * 32;
    const int d0 = blockIdx.z * 32;
    const int tx = threadIdx.x, ty = threadIdx.y;
    const float* src = W3 + (size_t)k * CB * CB;
    float* dst = W3t + (size_t)k * CB * CB;
#pragma unroll
    for (int yy = 0; yy < 32; yy += 8)
        sm[ty + yy][tx] = src[(size_t)(c0 + ty + yy) * CB + d0 + tx];
    __syncthreads();
#pragma unroll
    for (int yy = 0; yy < 32; yy += 8)
        dst[(size_t)(d0 + ty + yy) * CB + c0 + tx] = sm[tx][ty + yy];
}

// ---------------------------------------------------------------------------
// Column statistics (deterministic 2-level reduction)
// ---------------------------------------------------------------------------
template<int C>
__global__ void col_partial_kernel(const float* __restrict__ A, int N,
                                   float* __restrict__ ps, float* __restrict__ pq)
{
    const int b = blockIdx.x;
    const int rows = (N + NPART - 1) / NPART;
    const int r0 = b * rows;
    const int r1 = (r0 + rows < N) ? (r0 + rows) : N;
    const int t = threadIdx.x;
    for (int c = t; c < C; c += 256) {
        float s0 = 0.f, s1 = 0.f, q0 = 0.f, q1 = 0.f;
        int r = r0;
        for (; r + 1 < r1; r += 2) {
            float v0 = A[(size_t)r * C + c];
            float v1 = A[(size_t)(r + 1) * C + c];
            s0 += v0; q0 = fmaf(v0, v0, q0);
            s1 += v1; q1 = fmaf(v1, v1, q1);
        }
        if (r < r1) {
            float v = A[(size_t)r * C + c];
            s0 += v; q0 = fmaf(v, v, q0);
        }
        ps[b * C + c] = s0 + s1;
        pq[b * C + c] = q0 + q1;
    }
}

template<int C>
__global__ void col_finalize_kernel(const float* __restrict__ ps, const float* __restrict__ pq,
                                    const float* __restrict__ g, const float* __restrict__ bta,
                                    float* __restrict__ scl, float* __restrict__ sft, int N)
{
    int c = blockIdx.x * blockDim.x + threadIdx.x;
    if (c >= C) return;
    float s = 0.f, q = 0.f;
    for (int b = 0; b < NPART; b++) { s += ps[b * C + c]; q += pq[b * C + c]; }
    float inv_n = 1.f / (float)N;
    float mu  = s * inv_n;
    float var = fmaf(-mu, mu, q * inv_n);
    float sc  = g[c] * rsqrtf(var + 1e-5f);
    scl[c] = sc;
    sft[c] = fmaf(-mu, sc, bta[c]);
}

// ---------------------------------------------------------------------------
// Elementwise BN+ReLU apply: act[n,c] = relu(scl[c]*v + sft[c])
// ---------------------------------------------------------------------------
template<int C>
__global__ void bn_act_kernel(const float* __restrict__ in,
                              const float* __restrict__ scl, const float* __restrict__ sft,
                              float* __restrict__ act, int N)
{
    const int total = N * (C / 4);
    for (int i = blockIdx.x * blockDim.x + threadIdx.x; i < total; i += gridDim.x * blockDim.x) {
        int cq = i % (C / 4);
        float4 v  = reinterpret_cast<const float4*>(in)[i];
        float4 s4 = reinterpret_cast<const float4*>(scl)[cq];
        float4 f4 = reinterpret_cast<const float4*>(sft)[cq];
        v.x = fmaxf(fmaf(v.x, s4.x, f4.x), 0.f);
        v.y = fmaxf(fmaf(v.y, s4.y, f4.y), 0.f);
        v.z = fmaxf(fmaf(v.z, s4.z, f4.z), 0.f);
        v.w = fmaxf(fmaf(v.w, s4.w, f4.w), 0.f);
        reinterpret_cast<float4*>(act)[i] = v;
    }
}

// ---------------------------------------------------------------------------
// Final: out[e, n] = relu(bn(c3)[n,e] + bn(sc)[n,e]) (transposed write)
// ---------------------------------------------------------------------------
__global__ void final_out_kernel(const float* __restrict__ c3, const float* __restrict__ sc,
                                 const float* __restrict__ s3, const float* __restrict__ t3,
                                 const float* __restrict__ s4, const float* __restrict__ t4,
                                 float* __restrict__ out, int N)
{
    __shared__ float sm[32][33];
    const int n0 = blockIdx.x * 32;
    const int e0 = blockIdx.y * 32;
    const int tx = threadIdx.x;
    const int ty = threadIdx.y;
    const int e  = e0 + tx;
    const float a3 = s3[e], b3v = t3[e], a4 = s4[e], b4v = t4[e];

#pragma unroll
    for (int yy = 0; yy < 32; yy += 8) {
        int n = n0 + ty + yy;
        float v = 0.f;
        if (n < N) {
            float p = fmaf(c3[(size_t)n * COUT + e], a3, b3v);
            float q = fmaf(sc[(size_t)n * COUT + e], a4, b4v);
            v = fmaxf(p + q, 0.f);
        }
        sm[tx][ty + yy] = v;
    }
    __syncthreads();
#pragma unroll
    for (int yy = 0; yy < 32; yy += 8) {
        int eo = e0 + ty + yy;
        int n  = n0 + tx;
        if (n < N) out[(size_t)eo * N + n] = sm[ty + yy][tx];
    }
}

// ---------------------------------------------------------------------------
// Launcher
// ---------------------------------------------------------------------------
template<class T>
static float* sym_addr(T& s) { void* p = nullptr; cudaGetSymbolAddress(&p, s); return (float*)p; }

extern "C" void kernel_launch(void* const* d_in, const int* in_sizes, int n_in,
                              void* d_out, int out_size)
{
    const float* x   = (const float*)d_in[0];
    const int*   ngh = (const int*)  d_in[1];
    const float* W1a = (const float*)d_in[2];
    const float* g1a = (const float*)d_in[3];
    const float* b1a = (const float*)d_in[4];
    const float* W3  = (const float*)d_in[5];
    const float* g3  = (const float*)d_in[6];
    const float* b3  = (const float*)d_in[7];
    const float* W1b = (const float*)d_in[8];
    const float* g1b = (const float*)d_in[9];
    const float* b1b = (const float*)d_in[10];
    const float* Wc  = (const float*)d_in[11];
    const float* gc  = (const float*)d_in[12];
    const float* bc  = (const float*)d_in[13];
    float* out = (float*)d_out;

    const int N = in_sizes[1] / KNB;
    if (N <= 0 || N > NMAX) return;

    cudaFuncSetAttribute(mma_gemm_kernel<0, 256>,
                         cudaFuncAttributeMaxDynamicSharedMemorySize, DSMEM_BYTES);
    cudaFuncSetAttribute(mma_gemm_kernel<0, 128>,
                         cudaFuncAttributeMaxDynamicSharedMemorySize, DSMEM_BYTES);
    cudaFuncSetAttribute(mma_gemm_kernel<1, 128>,
                         cudaFuncAttributeMaxDynamicSharedMemorySize, DSMEM_BYTES);

    float* h   = sym_addr(g_h);
    float* c1  = sym_addr(g_c1);
    float* a1  = sym_addr(g_a1);
    float* c2  = sym_addr(g_c2);
    float* a2  = sym_addr(g_a2);
    float* c3  = sym_addr(g_c3);
    float* scv = sym_addr(g_sc);
    float* W3t = sym_addr(g_W3t);
    float* ps  = sym_addr(g_ps);
    float* pq  = sym_addr(g_pq);
    float* s1  = sym_addr(g_s1); float* t1 = sym_addr(g_t1);
    float* s2  = sym_addr(g_s2); float* t2 = sym_addr(g_t2);
    float* s3  = sym_addr(g_s3); float* t3 = sym_addr(g_t3);
    float* s4  = sym_addr(g_s4); float* t4 = sym_addr(g_t4);

    const int mb = (N + 127) / 128;

    // Prep: transpose x -> h [N, Cin], W3 -> W3t [k][d][c]
    transpose_x_kernel<<<dim3((N + 31) / 32, CIN / 32), dim3(32, 8)>>>(x, h, N);
    transpose_w3_kernel<<<dim3(KNB, CB / 32, CB / 32), dim3(32, 8)>>>(W3, W3t);

    // c1pre = h @ W1a^T            [N, 128]
    mma_gemm_kernel<0, 256><<<dim3(mb, 1), 256, DSMEM_BYTES>>>(h, W1a, nullptr, c1, N, CB);
    col_partial_kernel<CB><<<NPART, 256>>>(c1, N, ps, pq);
    col_finalize_kernel<CB><<<1, CB>>>(ps, pq, g1a, b1a, s1, t1, N);
    bn_act_kernel<CB><<<1024, 256>>>(c1, s1, t1, a1, N);

    // c2pre = octree_conv(act1)    [N, 128]
    mma_gemm_kernel<1, 128><<<dim3(mb, 1), 256, DSMEM_BYTES>>>(a1, W3t, ngh, c2, N, CB);
    col_partial_kernel<CB><<<NPART, 256>>>(c2, N, ps, pq);
    col_finalize_kernel<CB><<<1, CB>>>(ps, pq, g3, b3, s2, t2, N);
    bn_act_kernel<CB><<<1024, 256>>>(c2, s2, t2, a2, N);

    // c3pre = act2 @ W1b^T         [N, 512]
    mma_gemm_kernel<0, 128><<<dim3(mb, COUT / 128), 256, DSMEM_BYTES>>>(a2, W1b, nullptr, c3, N, COUT);
    // scpre = h @ Wc^T             [N, 512]
    mma_gemm_kernel<0, 256><<<dim3(mb, COUT / 128), 256, DSMEM_BYTES>>>(h, Wc, nullptr, scv, N, COUT);

    col_partial_kernel<COUT><<<NPART, 256>>>(c3, N, ps, pq);
    col_finalize_kernel<COUT><<<2, 256>>>(ps, pq, g1b, b1b, s3, t3, N);
    col_partial_kernel<COUT><<<NPART, 256>>>(scv, N, ps, pq);
    col_finalize_kernel<COUT><<<2, 256>>>(ps, pq, gc, bc, s4, t4, N);

    // out = relu(bn(c3pre) + bn(scpre))^T
    final_out_kernel<<<dim3((N + 31) / 32, COUT / 32), dim3(32, 8)>>>(
        c3, scv, s3, t3, s4, t4, out, N);
}

// round 12
// speedup vs baseline: 2.6723x; 1.0607x over previous
#include <cuda_runtime.h>
#include <cstdint>
#include <cstddef>

#define CIN   256
#define CB    128
#define COUT  512
#define KNB   27
#define NMAX  61440
#define PBLK  296          // partial-stat blocks (2 waves of 148)

// SMEM tile: [128 rows][68 floats] (64 data + 4 pad), double-buffered A+B
#define ROWF  68
static constexpr int STAGE_BYTES = 128 * ROWF * 4;             // 34816 per tile
static constexpr int DSMEM_BYTES = 4 * STAGE_BYTES + 256;      // 2 stages x (A+B)
static constexpr int MAXSLICES   = PBLK * 4;                   // C=128 -> 4 substripes

// ---------------------------------------------------------------------------
// Scratch (device globals; no cudaMalloc allowed)
// ---------------------------------------------------------------------------
__device__ float g_h   [NMAX * CIN];       // x transposed -> [N, Cin]  (tf32-rounded)
__device__ float g_c1  [NMAX * CB];        // pre-BN conv1a out [N, CB]
__device__ float g_a1  [NMAX * CB];        // relu(bn(c1)) tf32 [N, CB]
__device__ float g_c2  [NMAX * CB];        // pre-BN octree out [N, CB]
__device__ float g_a2  [NMAX * CB];        // relu(bn(c2)) tf32 [N, CB]
__device__ float g_c3  [NMAX * COUT];      // pre-BN conv1b out [N, COUT]
__device__ float g_sc  [NMAX * COUT];      // pre-BN shortcut   [N, COUT]
__device__ float g_W3t [KNB * CB * CB];    // W3 transposed [k][d][c] (tf32-rounded)
__device__ float g_W1ar[CB * CIN];         // tf32-rounded weights
__device__ float g_W1br[COUT * CB];
__device__ float g_Wcr [COUT * CIN];
__device__ float g_ps  [MAXSLICES * COUT / 4 * 4];  // partial sums
__device__ float g_pq  [MAXSLICES * COUT / 4 * 4];
__device__ float g_s1[CB],   g_t1[CB];
__device__ float g_s2[CB],   g_t2[CB];
__device__ float g_s3[COUT], g_t3[COUT];
__device__ float g_s4[COUT], g_t4[COUT];

// ---------------------------------------------------------------------------
// PTX helpers (baseline PTX only — no arch-specific 'a' features)
// ---------------------------------------------------------------------------
__device__ __forceinline__ uint32_t smem_u32(const void* p) {
    uint32_t a;
    asm("{ .reg .u64 t; cvta.to.shared.u64 t, %1; cvt.u32.u64 %0, t; }" : "=r"(a) : "l"(p));
    return a;
}
__device__ __forceinline__ void cp_async16(uint32_t dst, const void* src, bool pred) {
    int sz = pred ? 16 : 0;
    asm volatile("cp.async.cg.shared.global [%0], [%1], 16, %2;"
                 :: "r"(dst), "l"(src), "r"(sz) : "memory");
}
#define CP_COMMIT() asm volatile("cp.async.commit_group;" ::: "memory")
#define CP_WAIT1()  asm volatile("cp.async.wait_group 1;" ::: "memory")
#define CP_WAIT0()  asm volatile("cp.async.wait_group 0;" ::: "memory")

__device__ __forceinline__ uint32_t f2tf32(float x) {
    uint32_t r;
    asm("cvt.rna.tf32.f32 %0, %1;" : "=r"(r) : "f"(x));
    return r;
}
__device__ __forceinline__ float roundtf(float x) { return __uint_as_float(f2tf32(x)); }

__device__ __forceinline__ void mma1688(float* d, const uint32_t* a, const uint32_t* b) {
    asm volatile(
        "mma.sync.aligned.m16n8k8.row.col.f32.tf32.tf32.f32 "
        "{%0,%1,%2,%3}, {%4,%5,%6,%7}, {%8,%9}, {%0,%1,%2,%3};"
        : "+f"(d[0]), "+f"(d[1]), "+f"(d[2]), "+f"(d[3])
        : "r"(a[0]), "r"(a[1]), "r"(a[2]), "r"(a[3]), "r"(b[0]), "r"(b[1]));
}

// ---------------------------------------------------------------------------
// Unified tf32 mma.sync GEMM. All operands are pre-rounded to tf32 in memory,
// so fragment loads are raw uint32 (no cvt in the mainloop).
// MODE 0: out[m, j] = sum_k A[m,k] * B[j,k];  A row-major [N, KDIM].
// MODE 1: octree conv: A rows gathered via neigh (tap-major), B = W3t[tap].
// Block tile 128(M) x 128(J) x 64(K); 8 warps (2x4); warp tile 64x32.
// ---------------------------------------------------------------------------
template<int MODE, int KDIM>
__global__ __launch_bounds__(256, 1)
void mma_gemm_kernel(const float* __restrict__ A, const float* __restrict__ B,
                     const int* __restrict__ neigh,
                     float* __restrict__ out, int N, int ldc)
{
    constexpr int NCH = (MODE == 1) ? KNB * 2 : KDIM / 64;

    extern __shared__ float smem[];
    float* As[2] = { smem,               smem + 2 * 128 * ROWF };
    float* Bs[2] = { smem + 128 * ROWF,  smem + 3 * 128 * ROWF };
    uint32_t as_u[2] = { smem_u32(As[0]), smem_u32(As[1]) };
    uint32_t bs_u[2] = { smem_u32(Bs[0]), smem_u32(Bs[1]) };

    const int t    = threadIdx.x;
    const int wid  = t >> 5;
    const int lane = t & 31;
    const int wm   = wid & 1;          // 2 warp-rows
    const int wn   = wid >> 1;         // 4 warp-cols
    const int m0   = blockIdx.x * 128;
    const int j0   = blockIdx.y * 128;

    // copy-lane mapping: 16 rows x 16 16B-segments per pass, x8 passes = 128 rows
    const int rm = t >> 4;             // row slot 0..15
    const int sv = t & 15;             // 16B segment 0..15

    float acc[4][4][4];
#pragma unroll
    for (int mi = 0; mi < 4; mi++)
#pragma unroll
        for (int ni = 0; ni < 4; ni++)
#pragma unroll
            for (int q = 0; q < 4; q++) acc[mi][ni][q] = 0.f;

    auto issue_copy = [&](int ch, int stg) {
        int tap, c0;
        if (MODE == 1) { tap = ch >> 1; c0 = (ch & 1) * 64; }
        else           { tap = 0;       c0 = ch * 64; }
        const float* Bg = (MODE == 1) ? (B + (size_t)tap * CB * CB) : B;
        constexpr int KB = (MODE == 1) ? CB : KDIM;

#pragma unroll
        for (int i = 0; i < 8; i++) {
            int m  = i * 16 + rm;
            int gm = m0 + m;
            const float* src;
            bool pred;
            if (MODE == 1) {
                int ng = (gm < N) ? neigh[(size_t)gm * KNB + tap] : N;
                pred = (ng < N);
                src  = A + (size_t)(pred ? ng : 0) * CB + c0 + sv * 4;
            } else {
                pred = (gm < N);
                src  = A + (size_t)(pred ? gm : 0) * KDIM + c0 + sv * 4;
            }
            cp_async16(as_u[stg] + (uint32_t)(m * ROWF + sv * 4) * 4u, src, pred);
        }
#pragma unroll
        for (int i = 0; i < 8; i++) {
            int j = i * 16 + rm;
            const float* src = Bg + (size_t)(j0 + j) * KB + c0 + sv * 4;
            cp_async16(bs_u[stg] + (uint32_t)(j * ROWF + sv * 4) * 4u, src, true);
        }
        CP_COMMIT();
    };

    issue_copy(0, 0);

    for (int ch = 0; ch < NCH; ch++) {
        const int stg = ch & 1;
        if (ch + 1 < NCH) { issue_copy(ch + 1, stg ^ 1); CP_WAIT1(); }
        else              { CP_WAIT0(); }
        __syncthreads();

        const uint32_t* Ab = reinterpret_cast<const uint32_t*>(As[stg]);
        const uint32_t* Bb = reinterpret_cast<const uint32_t*>(Bs[stg]);
        const int ar = wm * 64 + (lane >> 2);      // + mi*16 (+8)
        const int bn = wn * 32 + (lane >> 2);      // + ni*8

#pragma unroll
        for (int kk = 0; kk < 8; kk++) {
            const int kc = kk * 8 + (lane & 3);
            uint32_t af[4][4], bf[4][2];
#pragma unroll
            for (int mi = 0; mi < 4; mi++) {
                const uint32_t* p = Ab + (ar + mi * 16) * ROWF + kc;
                af[mi][0] = p[0];
                af[mi][1] = p[8 * ROWF];
                af[mi][2] = p[4];
                af[mi][3] = p[8 * ROWF + 4];
            }
#pragma unroll
            for (int ni = 0; ni < 4; ni++) {
                const uint32_t* p = Bb + (bn + ni * 8) * ROWF + kc;
                bf[ni][0] = p[0];
                bf[ni][1] = p[4];
            }
#pragma unroll
            for (int mi = 0; mi < 4; mi++)
#pragma unroll
                for (int ni = 0; ni < 4; ni++)
                    mma1688(acc[mi][ni], af[mi], bf[ni]);
        }
        __syncthreads();
    }

    // ---- epilogue ----
    const int er = m0 + wm * 64 + (lane >> 2);
    const int ec = j0 + wn * 32 + 2 * (lane & 3);
#pragma unroll
    for (int mi = 0; mi < 4; mi++) {
        int r0 = er + mi * 16, r1 = r0 + 8;
#pragma unroll
        for (int ni = 0; ni < 4; ni++) {
            int c = ec + ni * 8;
            if (r0 < N)
                *reinterpret_cast<float2*>(out + (size_t)r0 * ldc + c) =
                    make_float2(acc[mi][ni][0], acc[mi][ni][1]);
            if (r1 < N)
                *reinterpret_cast<float2*>(out + (size_t)r1 * ldc + c) =
                    make_float2(acc[mi][ni][2], acc[mi][ni][3]);
        }
    }
}

// ---------------------------------------------------------------------------
// Transposes (tf32-round on store — these feed GEMM A/B operands only)
// ---------------------------------------------------------------------------
__global__ void transpose_x_kernel(const float* __restrict__ x, float* __restrict__ h, int N)
{
    __shared__ float sm[32][33];
    const int n0 = blockIdx.x * 32;
    const int c0 = blockIdx.y * 32;
    const int tx = threadIdx.x, ty = threadIdx.y;
#pragma unroll
    for (int yy = 0; yy < 32; yy += 8) {
        int n = n0 + tx;
        sm[ty + yy][tx] = (n < N) ? x[(size_t)(c0 + ty + yy) * N + n] : 0.f;
    }
    __syncthreads();
#pragma unroll
    for (int yy = 0; yy < 32; yy += 8) {
        int n = n0 + ty + yy;
        if (n < N) h[(size_t)n * CIN + c0 + tx] = roundtf(sm[tx][ty + yy]);
    }
}

__global__ void transpose_w3_kernel(const float* __restrict__ W3, float* __restrict__ W3t)
{
    __shared__ float sm[32][33];
    const int k  = blockIdx.x;
    const int c0 = blockIdx.y * 32;
    const int d0 = blockIdx.z * 32;
    const int tx = threadIdx.x, ty = threadIdx.y;
    const float* src = W3 + (size_t)k * CB * CB;
    float* dst = W3t + (size_t)k * CB * CB;
#pragma unroll
    for (int yy = 0; yy < 32; yy += 8)
        sm[ty + yy][tx] = src[(size_t)(c0 + ty + yy) * CB + d0 + tx];
    __syncthreads();
#pragma unroll
    for (int yy = 0; yy < 32; yy += 8)
        dst[(size_t)(d0 + ty + yy) * CB + c0 + tx] = roundtf(sm[tx][ty + yy]);
}

// tf32-round elementwise copy (for 1x1 weights)
__global__ void round_tf32_kernel(const float* __restrict__ in, float* __restrict__ out, int n4)
{
    int i = blockIdx.x * blockDim.x + threadIdx.x;
    if (i >= n4) return;
    float4 v = reinterpret_cast<const float4*>(in)[i];
    v.x = roundtf(v.x); v.y = roundtf(v.y); v.z = roundtf(v.z); v.w = roundtf(v.w);
    reinterpret_cast<float4*>(out)[i] = v;
}

// ---------------------------------------------------------------------------
// Column statistics (deterministic fixed-partition, float4 vectorized)
// blockDim = 128 threads = (C/4) float4-columns x SUB row-substripes.
// ---------------------------------------------------------------------------
template<int C>
__global__ void col_partial_kernel(const float* __restrict__ A, int N,
                                   float* __restrict__ ps, float* __restrict__ pq)
{
    constexpr int C4  = C / 4;
    constexpr int SUB = 128 / C4;             // C=512 -> 1, C=128 -> 4
    const int c4    = threadIdx.x % C4;
    const int sub   = threadIdx.x / C4;
    const int P     = gridDim.x * SUB;
    const int slice = blockIdx.x * SUB + sub;
    const int rows  = (N + P - 1) / P;
    const int r0    = slice * rows;
    const int r1    = (r0 + rows < N) ? (r0 + rows) : N;

    float4 s = make_float4(0.f, 0.f, 0.f, 0.f);
    float4 q = make_float4(0.f, 0.f, 0.f, 0.f);
    for (int r = r0; r < r1; r++) {
        float4 v = *reinterpret_cast<const float4*>(A + (size_t)r * C + c4 * 4);
        s.x += v.x; q.x = fmaf(v.x, v.x, q.x);
        s.y += v.y; q.y = fmaf(v.y, v.y, q.y);
        s.z += v.z; q.z = fmaf(v.z, v.z, q.z);
        s.w += v.w; q.w = fmaf(v.w, v.w, q.w);
    }
    *reinterpret_cast<float4*>(ps + (size_t)slice * C + c4 * 4) = s;
    *reinterpret_cast<float4*>(pq + (size_t)slice * C + c4 * 4) = q;
}

template<int C>
__global__ void col_finalize_kernel(const float* __restrict__ ps, const float* __restrict__ pq,
                                    const float* __restrict__ g, const float* __restrict__ bta,
                                    float* __restrict__ scl, float* __restrict__ sft,
                                    int N, int nslices)
{
    int c = blockIdx.x * blockDim.x + threadIdx.x;
    if (c >= C) return;
    float s = 0.f, q = 0.f;
    for (int b = 0; b < nslices; b++) { s += ps[(size_t)b * C + c]; q += pq[(size_t)b * C + c]; }
    float inv_n = 1.f / (float)N;
    float mu  = s * inv_n;
    float var = fmaf(-mu, mu, q * inv_n);
    float sc  = g[c] * rsqrtf(var + 1e-5f);
    scl[c] = sc;
    sft[c] = fmaf(-mu, sc, bta[c]);
}

// ---------------------------------------------------------------------------
// Elementwise BN+ReLU apply with tf32 rounding (feeds GEMM A operands)
// ---------------------------------------------------------------------------
template<int C>
__global__ void bn_act_kernel(const float* __restrict__ in,
                              const float* __restrict__ scl, const float* __restrict__ sft,
                              float* __restrict__ act, int N)
{
    const int total = N * (C / 4);
    for (int i = blockIdx.x * blockDim.x + threadIdx.x; i < total; i += gridDim.x * blockDim.x) {
        int cq = i % (C / 4);
        float4 v  = reinterpret_cast<const float4*>(in)[i];
        float4 s4 = reinterpret_cast<const float4*>(scl)[cq];
        float4 f4 = reinterpret_cast<const float4*>(sft)[cq];
        v.x = roundtf(fmaxf(fmaf(v.x, s4.x, f4.x), 0.f));
        v.y = roundtf(fmaxf(fmaf(v.y, s4.y, f4.y), 0.f));
        v.z = roundtf(fmaxf(fmaf(v.z, s4.z, f4.z), 0.f));
        v.w = roundtf(fmaxf(fmaf(v.w, s4.w, f4.w), 0.f));
        reinterpret_cast<float4*>(act)[i] = v;
    }
}

// ---------------------------------------------------------------------------
// Final: out[e, n] = relu(bn(c3)[n,e] + bn(sc)[n,e]) (transposed write)
// ---------------------------------------------------------------------------
__global__ void final_out_kernel(const float* __restrict__ c3, const float* __restrict__ sc,
                                 const float* __restrict__ s3, const float* __restrict__ t3,
                                 const float* __restrict__ s4, const float* __restrict__ t4,
                                 float* __restrict__ out, int N)
{
    __shared__ float sm[32][33];
    const int n0 = blockIdx.x * 32;
    const int e0 = blockIdx.y * 32;
    const int tx = threadIdx.x;
    const int ty = threadIdx.y;
    const int e  = e0 + tx;
    const float a3 = s3[e], b3v = t3[e], a4 = s4[e], b4v = t4[e];

#pragma unroll
    for (int yy = 0; yy < 32; yy += 8) {
        int n = n0 + ty + yy;
        float v = 0.f;
        if (n < N) {
            float p = fmaf(c3[(size_t)n * COUT + e], a3, b3v);
            float q = fmaf(sc[(size_t)n * COUT + e], a4, b4v);
            v = fmaxf(p + q, 0.f);
        }
        sm[tx][ty + yy] = v;
    }
    __syncthreads();
#pragma unroll
    for (int yy = 0; yy < 32; yy += 8) {
        int eo = e0 + ty + yy;
        int n  = n0 + tx;
        if (n < N) out[(size_t)eo * N + n] = sm[ty + yy][tx];
    }
}

// ---------------------------------------------------------------------------
// Launcher
// ---------------------------------------------------------------------------
template<class T>
static float* sym_addr(T& s) { void* p = nullptr; cudaGetSymbolAddress(&p, s); return (float*)p; }

extern "C" void kernel_launch(void* const* d_in, const int* in_sizes, int n_in,
                              void* d_out, int out_size)
{
    const float* x   = (const float*)d_in[0];
    const int*   ngh = (const int*)  d_in[1];
    const float* W1a = (const float*)d_in[2];
    const float* g1a = (const float*)d_in[3];
    const float* b1a = (const float*)d_in[4];
    const float* W3  = (const float*)d_in[5];
    const float* g3  = (const float*)d_in[6];
    const float* b3  = (const float*)d_in[7];
    const float* W1b = (const float*)d_in[8];
    const float* g1b = (const float*)d_in[9];
    const float* b1b = (const float*)d_in[10];
    const float* Wc  = (const float*)d_in[11];
    const float* gc  = (const float*)d_in[12];
    const float* bc  = (const float*)d_in[13];
    float* out = (float*)d_out;

    const int N = in_sizes[1] / KNB;
    if (N <= 0 || N > NMAX) return;

    cudaFuncSetAttribute(mma_gemm_kernel<0, 256>,
                         cudaFuncAttributeMaxDynamicSharedMemorySize, DSMEM_BYTES);
    cudaFuncSetAttribute(mma_gemm_kernel<0, 128>,
                         cudaFuncAttributeMaxDynamicSharedMemorySize, DSMEM_BYTES);
    cudaFuncSetAttribute(mma_gemm_kernel<1, 128>,
                         cudaFuncAttributeMaxDynamicSharedMemorySize, DSMEM_BYTES);

    float* h    = sym_addr(g_h);
    float* c1   = sym_addr(g_c1);
    float* a1   = sym_addr(g_a1);
    float* c2   = sym_addr(g_c2);
    float* a2   = sym_addr(g_a2);
    float* c3   = sym_addr(g_c3);
    float* scv  = sym_addr(g_sc);
    float* W3t  = sym_addr(g_W3t);
    float* w1ar = sym_addr(g_W1ar);
    float* w1br = sym_addr(g_W1br);
    float* wcr  = sym_addr(g_Wcr);
    float* ps   = sym_addr(g_ps);
    float* pq   = sym_addr(g_pq);
    float* s1   = sym_addr(g_s1); float* t1 = sym_addr(g_t1);
    float* s2   = sym_addr(g_s2); float* t2 = sym_addr(g_t2);
    float* s3   = sym_addr(g_s3); float* t3 = sym_addr(g_t3);
    float* s4   = sym_addr(g_s4); float* t4 = sym_addr(g_t4);

    const int mb = (N + 127) / 128;
    const int sl128 = PBLK * 4;   // slices for C=128
    const int sl512 = PBLK * 1;   // slices for C=512

    // Prep: transpose + tf32-round all GEMM operands
    transpose_x_kernel<<<dim3((N + 31) / 32, CIN / 32), dim3(32, 8)>>>(x, h, N);
    transpose_w3_kernel<<<dim3(KNB, CB / 32, CB / 32), dim3(32, 8)>>>(W3, W3t);
    round_tf32_kernel<<<(CB * CIN / 4 + 255) / 256, 256>>>(W1a, w1ar, CB * CIN / 4);
    round_tf32_kernel<<<(COUT * CB / 4 + 255) / 256, 256>>>(W1b, w1br, COUT * CB / 4);
    round_tf32_kernel<<<(COUT * CIN / 4 + 255) / 256, 256>>>(Wc, wcr, COUT * CIN / 4);

    // c1pre = h @ W1a^T            [N, 128]
    mma_gemm_kernel<0, 256><<<dim3(mb, 1), 256, DSMEM_BYTES>>>(h, w1ar, nullptr, c1, N, CB);
    col_partial_kernel<CB><<<PBLK, 128>>>(c1, N, ps, pq);
    col_finalize_kernel<CB><<<1, CB>>>(ps, pq, g1a, b1a, s1, t1, N, sl128);
    bn_act_kernel<CB><<<1024, 256>>>(c1, s1, t1, a1, N);

    // c2pre = octree_conv(act1)    [N, 128]
    mma_gemm_kernel<1, 128><<<dim3(mb, 1), 256, DSMEM_BYTES>>>(a1, W3t, ngh, c2, N, CB);
    col_partial_kernel<CB><<<PBLK, 128>>>(c2, N, ps, pq);
    col_finalize_kernel<CB><<<1, CB>>>(ps, pq, g3, b3, s2, t2, N, sl128);
    bn_act_kernel<CB><<<1024, 256>>>(c2, s2, t2, a2, N);

    // c3pre = act2 @ W1b^T         [N, 512]
    mma_gemm_kernel<0, 128><<<dim3(mb, COUT / 128), 256, DSMEM_BYTES>>>(a2, w1br, nullptr, c3, N, COUT);
    // scpre = h @ Wc^T             [N, 512]
    mma_gemm_kernel<0, 256><<<dim3(mb, COUT / 128), 256, DSMEM_BYTES>>>(h, wcr, nullptr, scv, N, COUT);

    col_partial_kernel<COUT><<<PBLK, 128>>>(c3, N, ps, pq);
    col_finalize_kernel<COUT><<<2, 256>>>(ps, pq, g1b, b1b, s3, t3, N, sl512);
    col_partial_kernel<COUT><<<PBLK, 128>>>(scv, N, ps, pq);
    col_finalize_kernel<COUT><<<2, 256>>>(ps, pq, gc, bc, s4, t4, N, sl512);

    // out = relu(bn(c3pre) + bn(scpre))^T
    final_out_kernel<<<dim3((N + 31) / 32, COUT / 32), dim3(32, 8)>>>(
        c3, scv, s3, t3, s4, t4, out, N);
}